// round 9
// baseline (speedup 1.0000x reference)
#include <cuda_runtime.h>
#include <math.h>

#define T_ 256
#define B_ 256
#define C_ 64
#define H_ 512
#define G_ 2048
#define K_ 640   // 512 (h) + 64 (c_c) + 64 (m)
#define NBLK 128

// ---- static device scratch ----
__device__ float g_v[T_*B_*C_];
__device__ float g_m[T_*B_*C_];
__device__ float g_d[T_*B_*C_];
__device__ float g_gh[T_*B_*H_];    // gamma_h (134MB)
__device__ float g_al[T_*B_*C_];
__device__ float g_A[B_*K_];        // [h_dec | c_c | m]
__device__ float g_h[B_*H_];
__device__ float g_Wcat[G_*K_];     // [u*4+gate][k]
__device__ float g_bias[G_];
__device__ float g_WhT[H_*C_];      // W_hist^T (coalesced per-lane c)
__device__ float g_WfT[C_*C_];      // W_feat^T, zero diagonal
__device__ float g_WcT[2*C_*C_];
__device__ float g_diag[C_];
__device__ unsigned g_bar[2][64];   // [grp][0]=arrive, [grp][32]=gen

// ---- f32x2 packed FMA helpers ----
__device__ __forceinline__ unsigned long long dup2(float a) {
    unsigned long long r;
    asm("mov.b64 %0, {%1,%1};" : "=l"(r) : "f"(a));
    return r;
}
__device__ __forceinline__ void ffma2(unsigned long long& d, unsigned long long a,
                                      unsigned long long b) {
    asm("fma.rn.f32x2 %0, %1, %2, %0;" : "+l"(d) : "l"(a), "l"(b));
}
__device__ __forceinline__ void fadd2(unsigned long long& d, unsigned long long b) {
    asm("add.rn.f32x2 %0, %0, %1;" : "+l"(d) : "l"(b));
}
__device__ __forceinline__ float2 upk2(unsigned long long v) {
    float2 f;
    asm("mov.b64 {%0,%1}, %2;" : "=f"(f.x), "=f"(f.y) : "l"(v));
    return f;
}

// ---- group-local grid barrier: 64 blocks, acq/rel ----
__device__ __forceinline__ void gbar(int grp) {
    __syncthreads();
    if (threadIdx.x == 0) {
        unsigned* arr = &g_bar[grp][0];
        unsigned* gen = &g_bar[grp][32];
        unsigned g0;
        asm volatile("ld.acquire.gpu.global.u32 %0, [%1];" : "=r"(g0) : "l"(gen));
        unsigned old;
        asm volatile("atom.acq_rel.gpu.global.add.u32 %0, [%1], 1;"
                     : "=r"(old) : "l"(arr));
        if (old == 63u) {
            asm volatile("st.relaxed.gpu.global.u32 [%0], 0;" :: "l"(arr));
            asm volatile("red.release.gpu.global.add.u32 [%0], 1;" :: "l"(gen));
        } else {
            unsigned g;
            do {
                __nanosleep(32);
                asm volatile("ld.acquire.gpu.global.u32 %0, [%1];" : "=r"(g) : "l"(gen));
            } while (g == g0);
        }
    }
    __syncthreads();
}

// ======================= preamble kernels =======================

__global__ void k_pack_w(const float* __restrict__ Wih, const float* __restrict__ Whh) {
    for (int i = blockIdx.x*blockDim.x + threadIdx.x; i < G_*K_; i += gridDim.x*blockDim.x) {
        int gp = i / K_, k = i % K_;
        int u = gp >> 2, gate = gp & 3;
        int go = gate*H_ + u;
        float w;
        if (k < H_)            w = Whh[go*H_ + k];
        else if (k < H_ + C_)  w = Wih[go*2*C_ + (k - H_)];
        else                   w = Wih[go*2*C_ + C_ + (k - H_ - C_)];
        g_Wcat[i] = w;
    }
}

__global__ void k_pack_misc(const float* __restrict__ Whist, const float* __restrict__ Wfeat,
                            const float* __restrict__ Wcomb, const float* __restrict__ bih,
                            const float* __restrict__ bhh,   const float* __restrict__ Wgx) {
    int tid = blockIdx.x*blockDim.x + threadIdx.x, n = gridDim.x*blockDim.x;
    for (int i = tid; i < H_*C_; i += n) { int u=i/C_, c=i%C_; g_WhT[i] = Whist[c*H_ + u]; }
    for (int i = tid; i < C_*C_; i += n) { int j=i/C_, c=i%C_; g_WfT[i] = (j==c)?0.f:Wfeat[c*C_ + j]; }
    for (int i = tid; i < 2*C_*C_; i += n) { int j=i/C_, c=i%C_; g_WcT[i] = Wcomb[c*2*C_ + j]; }
    for (int i = tid; i < C_; i += n) g_diag[i] = Wgx[i*C_ + i];
    for (int i = tid; i < G_; i += n) { int u=i>>2, g=i&3; int go=g*H_+u; g_bias[i] = bih[go] + bhh[go]; }
    for (int i = tid; i < B_*H_; i += n) g_h[i] = 0.f;
}

__global__ void k_prep(const float* __restrict__ data) {
    int id = blockIdx.x*blockDim.x + threadIdx.x;
    if (id >= B_*C_) return;
    int b = id / C_, c = id % C_;
    float dec = 1.f, m_prev = 1.f;
    for (int t = 0; t < T_; t++) {
        float x = data[(b*T_ + t)*C_ + c];
        float m = (x != x) ? 0.f : 1.f;
        float v = (x != x) ? 0.f : x;
        float del;
        if (t == 0) del = 0.f;
        else if (t == 1) del = 1.f;
        else { dec = (m_prev == 1.f) ? 1.f : dec + 1.f; del = dec; }
        int o = (t*B_ + b)*C_ + c;
        g_v[o] = v; g_m[o] = m; g_d[o] = del;
        m_prev = m;
    }
}

__global__ void __launch_bounds__(256) k_gammaH(const float* __restrict__ Wgh,
                                                const float* __restrict__ bgh) {
    __shared__ __align__(16) float As[2][32][68];
    __shared__ __align__(16) float Ws[2][32][68];
    int m0 = (blockIdx.x >> 3) << 6;
    int n0 = (blockIdx.x & 7) << 6;
    int tid = threadIdx.x, tx = tid & 15, ty = tid >> 4;
    int mm = tid >> 3, kk4 = (tid & 7) << 2;

    unsigned long long acc[4][2] = {};
    #define STAGE_G(buf, kc) { \
        float4 a0 = *(const float4*)&g_d[(m0+mm)*C_ + (kc) + kk4]; \
        float4 a1 = *(const float4*)&g_d[(m0+mm+32)*C_ + (kc) + kk4]; \
        float4 w0 = *(const float4*)&Wgh[(n0+mm)*C_ + (kc) + kk4]; \
        float4 w1 = *(const float4*)&Wgh[(n0+mm+32)*C_ + (kc) + kk4]; \
        As[buf][kk4+0][mm]=a0.x; As[buf][kk4+1][mm]=a0.y; As[buf][kk4+2][mm]=a0.z; As[buf][kk4+3][mm]=a0.w; \
        As[buf][kk4+0][mm+32]=a1.x; As[buf][kk4+1][mm+32]=a1.y; As[buf][kk4+2][mm+32]=a1.z; As[buf][kk4+3][mm+32]=a1.w; \
        Ws[buf][kk4+0][mm]=w0.x; Ws[buf][kk4+1][mm]=w0.y; Ws[buf][kk4+2][mm]=w0.z; Ws[buf][kk4+3][mm]=w0.w; \
        Ws[buf][kk4+0][mm+32]=w1.x; Ws[buf][kk4+1][mm+32]=w1.y; Ws[buf][kk4+2][mm+32]=w1.z; Ws[buf][kk4+3][mm+32]=w1.w; }

    STAGE_G(0, 0);
    __syncthreads();
    #pragma unroll
    for (int ch = 0; ch < 2; ch++) {
        int buf = ch & 1;
        if (ch < 1) STAGE_G(1, 32);
        #pragma unroll
        for (int kk = 0; kk < 32; kk++) {
            float4 a = *(const float4*)&As[buf][kk][tx*4];
            ulonglong2 w = *(const ulonglong2*)&Ws[buf][kk][ty*4];
            unsigned long long a0 = dup2(a.x), a1 = dup2(a.y), a2 = dup2(a.z), a3 = dup2(a.w);
            ffma2(acc[0][0], a0, w.x); ffma2(acc[0][1], a0, w.y);
            ffma2(acc[1][0], a1, w.x); ffma2(acc[1][1], a1, w.y);
            ffma2(acc[2][0], a2, w.x); ffma2(acc[2][1], a2, w.y);
            ffma2(acc[3][0], a3, w.x); ffma2(acc[3][1], a3, w.y);
        }
        __syncthreads();
    }
    int u0 = n0 + ty*4;
    float4 b4 = *(const float4*)&bgh[u0];
    #pragma unroll
    for (int mi = 0; mi < 4; mi++) {
        int row = m0 + tx*4 + mi;
        float2 p0 = upk2(acc[mi][0]), p1 = upk2(acc[mi][1]);
        float4 v;
        v.x = expf(-fmaxf(p0.x + b4.x, 0.f));
        v.y = expf(-fmaxf(p0.y + b4.y, 0.f));
        v.z = expf(-fmaxf(p1.x + b4.z, 0.f));
        v.w = expf(-fmaxf(p1.y + b4.w, 0.f));
        *(float4*)&g_gh[row*H_ + u0] = v;
    }
    #undef STAGE_G
}

__global__ void k_alpha(const float* __restrict__ bgx, const float* __restrict__ bcomb) {
    __shared__ float gx[4][C_], ms[4][C_];
    int row0 = blockIdx.x * 8;
    int r = threadIdx.x >> 6, i = threadIdx.x & 63;
    for (int p = 0; p < 2; p++) {
        int row = row0 + p*4 + r;
        float d = g_d[row*C_ + i], m = g_m[row*C_ + i];
        gx[r][i] = expf(-fmaxf(d*g_diag[i] + bgx[i], 0.f));
        ms[r][i] = m;
        __syncthreads();
        float acc = bcomb[i];
        #pragma unroll 8
        for (int j = 0; j < C_; j++) acc += gx[r][j] * g_WcT[j*C_ + i];
        #pragma unroll 8
        for (int j = 0; j < C_; j++) acc += ms[r][j] * g_WcT[(C_ + j)*C_ + i];
        g_al[row*C_ + i] = acc;
        __syncthreads();
    }
}

// ======================= persistent sequential kernel =======================
// Tiling: 2 m-tiles (128 rows) x 64 n-tiles (32 gate cols). blk: mt=blk&1, nt=blk>>1.
// smem layout (floats):
#define SW_OFF   0                       // W dup slice [640][68], 64 dup-cols used
#define SW_SZ    (K_*68)                 // 43520
#define AS_OFF   (SW_OFF + SW_SZ)        // A staging [2][32][132]
#define AS_SZ    (2*32*132)              // 8448
#define HD_OFF   (AS_OFF + AS_SZ)        // 2*512
#define PART_OFF (HD_OFF + 2*H_)         // 256
#define XH_OFF   (PART_OFF + 256)
#define XC_OFF   (XH_OFF + 2*C_)
#define MS_OFF   (XC_OFF + 2*C_)
#define VS_OFF   (MS_OFF + 2*C_)
#define SMEM_FLOATS (VS_OFF + 2*C_)      // 53760 floats = 215040 B

__global__ void __launch_bounds__(256, 1) k_seq(const float* __restrict__ bhist,
                                                const float* __restrict__ bfeat,
                                                float* __restrict__ out) {
    extern __shared__ __align__(16) float sm[];
    float* Wsm  = sm + SW_OFF;
    float* As   = sm + AS_OFF;
    float* hd   = sm + HD_OFF;
    float* part = sm + PART_OFF;
    float* xh   = sm + XH_OFF;
    float* xc   = sm + XC_OFF;
    float* msh  = sm + MS_OFF;
    float* vsh  = sm + VS_OFF;

    int tid = threadIdx.x, blk = blockIdx.x;
    int mt = blk & 1, nt = blk >> 1;
    int m0g = mt << 7;                   // 128-row m-tile base
    int n0g = nt << 5;                   // 32-col n-tile base
    int tx = tid & 15, ty = tid >> 4;
    int b0 = m0g + nt*2;                 // phase-A rows (within own group)
    int ml = tid & 127, kg = tid >> 7;   // A staging map

    // prologue: duplicated W slice to smem; per-thread bias for its 2 gate cols
    for (int i = tid; i < 32*K_; i += 256) {
        int j = i / K_, k = i - j*K_;
        float w = g_Wcat[(n0g + j)*K_ + k];
        Wsm[k*68 + 2*j]     = w;
        Wsm[k*68 + 2*j + 1] = w;
    }
    float bc0 = g_bias[n0g + ty*2];
    float bc1 = g_bias[n0g + ty*2 + 1];
    int u_ep = (nt << 3) + (ty >> 1);    // this thread's LSTM unit
    float cst[4] = {0.f, 0.f, 0.f, 0.f};
    __syncthreads();

    for (int t = 0; t < T_; t++) {
        // ---------------- phase A: rows b0, b0+1 ----------------
        if (tid < 128) {
            int r = tid >> 6, c = tid & 63;
            int o = (t*B_ + b0 + r)*C_ + c;
            msh[tid] = g_m[o]; vsh[tid] = g_v[o];
        }
        {
            int r = tid >> 7, u0 = (tid & 127) * 4;
            int b = b0 + r;
            float4 h4 = __ldcg((const float4*)&g_h[b*H_ + u0]);
            float4 gh4 = *(const float4*)&g_gh[(t*B_ + b)*H_ + u0];
            float4 v = make_float4(h4.x*gh4.x, h4.y*gh4.y, h4.z*gh4.z, h4.w*gh4.w);
            *(float4*)&hd[r*H_ + u0] = v;
            __stcg((float4*)&g_A[b*K_ + u0], v);
        }
        __syncthreads();
        {   // x_h GEMV: coalesced g_WhT (lanes span c)
            int r = tid >> 7, half = (tid >> 6) & 1, c = tid & 63;
            const float* hp = &hd[r*H_ + half*256];
            const float* wp = &g_WhT[(half*256)*C_ + c];
            float a0 = 0.f, a1 = 0.f, a2 = 0.f, a3 = 0.f;
            #pragma unroll 8
            for (int u = 0; u < 256; u += 4) {
                a0 += hp[u+0] * wp[(u+0)*C_];
                a1 += hp[u+1] * wp[(u+1)*C_];
                a2 += hp[u+2] * wp[(u+2)*C_];
                a3 += hp[u+3] * wp[(u+3)*C_];
            }
            part[tid] = (a0 + a1) + (a2 + a3);
        }
        __syncthreads();
        if (tid < 128) {
            int r = tid >> 6, c = tid & 63;
            float x_h = part[r*128 + c] + part[r*128 + 64 + c] + bhist[c];
            xh[tid] = x_h;
            float m = msh[tid], v = vsh[tid];
            xc[tid] = m*v + (1.f - m)*x_h;
        }
        __syncthreads();
        if (tid < 128) {
            int r = tid >> 6, i = tid & 63;
            int b = b0 + r;
            float z = bfeat[i];
            const float* xp = &xc[r*C_];
            #pragma unroll 8
            for (int j = 0; j < C_; j++) z += xp[j] * g_WfT[j*C_ + i];
            float al = g_al[(t*B_ + b)*C_ + i];
            float x_h = xh[tid];
            float ch = al*z + (1.f - al)*x_h;
            float m = msh[tid], v = vsh[tid];
            float cc = m*v + (1.f - m)*ch;
            out[(b*T_ + t)*C_ + i] = cc;
            __stcg(&g_A[b*K_ + H_ + i], cc);
            __stcg(&g_A[b*K_ + H_ + C_ + i], m);
        }
        gbar(mt);   // group's g_A complete

        // ---------------- phase B: 128m x 32n tile, dup-W in smem ----------------
        unsigned long long acc[2][4] = {};   // [n][m-pair]
        #define STAGE_A(buf, kc) { \
            float* Ab = As + (buf)*(32*132); \
            _Pragma("unroll") \
            for (int q = 0; q < 4; q++) { \
                float4 a = __ldcg((const float4*)&g_A[(m0g + ml)*K_ + (kc) + kg*16 + q*4]); \
                int kk = kg*16 + q*4; \
                Ab[(kk+0)*132 + ml] = a.x; Ab[(kk+1)*132 + ml] = a.y; \
                Ab[(kk+2)*132 + ml] = a.z; Ab[(kk+3)*132 + ml] = a.w; \
            } }

        STAGE_A(0, 0);
        __syncthreads();
        for (int ch = 0; ch < 20; ch++) {
            int buf = ch & 1;
            if (ch < 19) STAGE_A(buf ^ 1, (ch + 1) * 32);
            const float* Ab = As + buf*(32*132);
            const float* Wb = Wsm + (ch*32)*68;
            #pragma unroll
            for (int kk = 0; kk < 32; kk++) {
                ulonglong2 a01 = *(const ulonglong2*)&Ab[kk*132 + tx*8];
                ulonglong2 a23 = *(const ulonglong2*)&Ab[kk*132 + tx*8 + 4];
                ulonglong2 w   = *(const ulonglong2*)&Wb[kk*68 + ty*4];
                ffma2(acc[0][0], a01.x, w.x); ffma2(acc[1][0], a01.x, w.y);
                ffma2(acc[0][1], a01.y, w.x); ffma2(acc[1][1], a01.y, w.y);
                ffma2(acc[0][2], a23.x, w.x); ffma2(acc[1][2], a23.x, w.y);
                ffma2(acc[0][3], a23.y, w.x); ffma2(acc[1][3], a23.y, w.y);
            }
            __syncthreads();
        }
        #undef STAGE_A

        // bias, then reassemble (i,f,g,o) across ty-parity partners (lane ^ 16)
        {
            unsigned long long bd0 = dup2(bc0), bd1 = dup2(bc1);
            #pragma unroll
            for (int p = 0; p < 4; p++) { fadd2(acc[0][p], bd0); fadd2(acc[1][p], bd1); }
            int sel = ty & 1;
            unsigned long long x0 = __shfl_xor_sync(0xffffffffu, sel ? acc[0][0] : acc[0][2], 16);
            unsigned long long x1 = __shfl_xor_sync(0xffffffffu, sel ? acc[0][1] : acc[0][3], 16);
            unsigned long long x2 = __shfl_xor_sync(0xffffffffu, sel ? acc[1][0] : acc[1][2], 16);
            unsigned long long x3 = __shfl_xor_sync(0xffffffffu, sel ? acc[1][1] : acc[1][3], 16);
            unsigned long long giP[2], gfP[2], ggP[2], goP[2];
            if (!sel) {
                giP[0]=acc[0][0]; giP[1]=acc[0][1]; gfP[0]=acc[1][0]; gfP[1]=acc[1][1];
                ggP[0]=x0;        ggP[1]=x1;        goP[0]=x2;        goP[1]=x3;
            } else {
                giP[0]=x0;        giP[1]=x1;        gfP[0]=x2;        gfP[1]=x3;
                ggP[0]=acc[0][2]; ggP[1]=acc[0][3]; goP[0]=acc[1][2]; goP[1]=acc[1][3];
            }
            int mbase = m0g + tx*8 + sel*4;
            #pragma unroll
            for (int p = 0; p < 2; p++) {
                float2 gi2 = upk2(giP[p]), gf2 = upk2(gfP[p]);
                float2 gg2 = upk2(ggP[p]), go2 = upk2(goP[p]);
                float gia[2] = {gi2.x, gi2.y}, gfa[2] = {gf2.x, gf2.y};
                float gga[2] = {gg2.x, gg2.y}, goa[2] = {go2.x, go2.y};
                #pragma unroll
                for (int q = 0; q < 2; q++) {
                    int mi = p*2 + q;
                    float co = cst[mi];
                    float si = 1.f/(1.f + expf(-gia[q]));
                    float sf = 1.f/(1.f + expf(-gfa[q]));
                    float so = 1.f/(1.f + expf(-goa[q]));
                    float cn = sf*co + si*tanhf(gga[q]);
                    cst[mi] = cn;
                    __stcg(&g_h[(mbase + mi)*H_ + u_ep], so*tanhf(cn));
                }
            }
        }
        gbar(mt);   // group's g_h complete
    }
}

extern "C" void kernel_launch(void* const* d_in, const int* in_sizes, int n_in,
                              void* d_out, int out_size) {
    const float* data  = (const float*)d_in[0];
    const float* Wih   = (const float*)d_in[1];
    const float* Whh   = (const float*)d_in[2];
    const float* bih   = (const float*)d_in[3];
    const float* bhh   = (const float*)d_in[4];
    const float* Wgh   = (const float*)d_in[5];
    const float* bgh   = (const float*)d_in[6];
    const float* Wgx   = (const float*)d_in[7];
    const float* bgx   = (const float*)d_in[8];
    const float* Whist = (const float*)d_in[9];
    const float* bhist = (const float*)d_in[10];
    const float* Wfeat = (const float*)d_in[11];
    const float* bfeat = (const float*)d_in[12];
    const float* Wcomb = (const float*)d_in[13];
    const float* bcomb = (const float*)d_in[14];
    float* out = (float*)d_out;

    static int smem_set = 0;
    if (!smem_set) {
        cudaFuncSetAttribute(k_seq, cudaFuncAttributeMaxDynamicSharedMemorySize,
                             SMEM_FLOATS * sizeof(float));
        smem_set = 1;
    }

    k_pack_w<<<2048, 256>>>(Wih, Whh);
    k_pack_misc<<<256, 256>>>(Whist, Wfeat, Wcomb, bih, bhh, Wgx);
    k_prep<<<64, 256>>>(data);
    k_gammaH<<<8192, 256>>>(Wgh, bgh);
    k_alpha<<<8192, 256>>>(bgx, bcomb);
    k_seq<<<NBLK, 256, SMEM_FLOATS * sizeof(float)>>>(bhist, bfeat, out);
}

// round 10
// speedup vs baseline: 1.7499x; 1.7499x over previous
#include <cuda_runtime.h>
#include <math.h>

#define T_ 256
#define B_ 256
#define C_ 64
#define H_ 512
#define G_ 2048
#define K_ 640   // 512 (h) + 64 (c_c) + 64 (m)
#define NBLK 128

// ---- static device scratch ----
__device__ float g_v[T_*B_*C_];
__device__ float g_m[T_*B_*C_];
__device__ float g_d[T_*B_*C_];
__device__ float g_gh[T_*B_*H_];    // gamma_h (134MB)
__device__ float g_al[T_*B_*C_];
__device__ float g_A[B_*K_];        // [h_dec | c_c | m]
__device__ float g_h[B_*H_];
__device__ float g_Wcat[G_*K_];     // [u*4+gate][k]
__device__ float g_bias[G_];
__device__ float g_WhT[H_*C_];      // W_hist^T (coalesced per-lane c)
__device__ float g_WfT[C_*C_];      // W_feat^T, zero diagonal
__device__ float g_WcT[2*C_*C_];
__device__ float g_diag[C_];
__device__ unsigned g_bar[4][64];   // [grp][0]=arrive, [grp][32]=gen

// ---- f32x2 packed FMA helpers ----
__device__ __forceinline__ unsigned long long dup2(float a) {
    unsigned long long r;
    asm("mov.b64 %0, {%1,%1};" : "=l"(r) : "f"(a));
    return r;
}
__device__ __forceinline__ void ffma2(unsigned long long& d, unsigned long long a,
                                      unsigned long long b) {
    asm("fma.rn.f32x2 %0, %1, %2, %0;" : "+l"(d) : "l"(a), "l"(b));
}
__device__ __forceinline__ float2 upk2(unsigned long long v) {
    float2 f;
    asm("mov.b64 {%0,%1}, %2;" : "=f"(f.x), "=f"(f.y) : "l"(v));
    return f;
}

// ---- group-local grid barrier: 32 blocks, acq/rel, poll via loads ----
__device__ __forceinline__ void gbar(int grp) {
    __syncthreads();
    if (threadIdx.x == 0) {
        unsigned* arr = &g_bar[grp][0];
        unsigned* gen = &g_bar[grp][32];
        unsigned g0;
        asm volatile("ld.acquire.gpu.global.u32 %0, [%1];" : "=r"(g0) : "l"(gen));
        unsigned old;
        asm volatile("atom.acq_rel.gpu.global.add.u32 %0, [%1], 1;"
                     : "=r"(old) : "l"(arr));
        if (old == 31u) {
            asm volatile("st.relaxed.gpu.global.u32 [%0], 0;" :: "l"(arr));
            asm volatile("red.release.gpu.global.add.u32 [%0], 1;" :: "l"(gen));
        } else {
            unsigned g;
            do {
                __nanosleep(32);
                asm volatile("ld.acquire.gpu.global.u32 %0, [%1];" : "=r"(g) : "l"(gen));
            } while (g == g0);
        }
    }
    __syncthreads();
}

// ======================= preamble kernels =======================

__global__ void k_pack_w(const float* __restrict__ Wih, const float* __restrict__ Whh) {
    for (int i = blockIdx.x*blockDim.x + threadIdx.x; i < G_*K_; i += gridDim.x*blockDim.x) {
        int gp = i / K_, k = i % K_;
        int u = gp >> 2, gate = gp & 3;
        int go = gate*H_ + u;
        float w;
        if (k < H_)            w = Whh[go*H_ + k];
        else if (k < H_ + C_)  w = Wih[go*2*C_ + (k - H_)];
        else                   w = Wih[go*2*C_ + C_ + (k - H_ - C_)];
        g_Wcat[i] = w;
    }
}

__global__ void k_pack_misc(const float* __restrict__ Whist, const float* __restrict__ Wfeat,
                            const float* __restrict__ Wcomb, const float* __restrict__ bih,
                            const float* __restrict__ bhh,   const float* __restrict__ Wgx) {
    int tid = blockIdx.x*blockDim.x + threadIdx.x, n = gridDim.x*blockDim.x;
    for (int i = tid; i < H_*C_; i += n) { int u=i/C_, c=i%C_; g_WhT[i] = Whist[c*H_ + u]; }
    for (int i = tid; i < C_*C_; i += n) { int j=i/C_, c=i%C_; g_WfT[i] = (j==c)?0.f:Wfeat[c*C_ + j]; }
    for (int i = tid; i < 2*C_*C_; i += n) { int j=i/C_, c=i%C_; g_WcT[i] = Wcomb[c*2*C_ + j]; }
    for (int i = tid; i < C_; i += n) g_diag[i] = Wgx[i*C_ + i];
    for (int i = tid; i < G_; i += n) { int u=i>>2, g=i&3; int go=g*H_+u; g_bias[i] = bih[go] + bhh[go]; }
    for (int i = tid; i < B_*H_; i += n) g_h[i] = 0.f;
}

__global__ void k_prep(const float* __restrict__ data) {
    int id = blockIdx.x*blockDim.x + threadIdx.x;
    if (id >= B_*C_) return;
    int b = id / C_, c = id % C_;
    float dec = 1.f, m_prev = 1.f;
    for (int t = 0; t < T_; t++) {
        float x = data[(b*T_ + t)*C_ + c];
        float m = (x != x) ? 0.f : 1.f;
        float v = (x != x) ? 0.f : x;
        float del;
        if (t == 0) del = 0.f;
        else if (t == 1) del = 1.f;
        else { dec = (m_prev == 1.f) ? 1.f : dec + 1.f; del = dec; }
        int o = (t*B_ + b)*C_ + c;
        g_v[o] = v; g_m[o] = m; g_d[o] = del;
        m_prev = m;
    }
}

__global__ void __launch_bounds__(256) k_gammaH(const float* __restrict__ Wgh,
                                                const float* __restrict__ bgh) {
    __shared__ __align__(16) float As[2][32][68];
    __shared__ __align__(16) float Ws[2][32][68];
    int m0 = (blockIdx.x >> 3) << 6;
    int n0 = (blockIdx.x & 7) << 6;
    int tid = threadIdx.x, tx = tid & 15, ty = tid >> 4;
    int mm = tid >> 3, kk4 = (tid & 7) << 2;

    unsigned long long acc[4][2] = {};
    #define STAGE_G(buf, kc) { \
        float4 a0 = *(const float4*)&g_d[(m0+mm)*C_ + (kc) + kk4]; \
        float4 a1 = *(const float4*)&g_d[(m0+mm+32)*C_ + (kc) + kk4]; \
        float4 w0 = *(const float4*)&Wgh[(n0+mm)*C_ + (kc) + kk4]; \
        float4 w1 = *(const float4*)&Wgh[(n0+mm+32)*C_ + (kc) + kk4]; \
        As[buf][kk4+0][mm]=a0.x; As[buf][kk4+1][mm]=a0.y; As[buf][kk4+2][mm]=a0.z; As[buf][kk4+3][mm]=a0.w; \
        As[buf][kk4+0][mm+32]=a1.x; As[buf][kk4+1][mm+32]=a1.y; As[buf][kk4+2][mm+32]=a1.z; As[buf][kk4+3][mm+32]=a1.w; \
        Ws[buf][kk4+0][mm]=w0.x; Ws[buf][kk4+1][mm]=w0.y; Ws[buf][kk4+2][mm]=w0.z; Ws[buf][kk4+3][mm]=w0.w; \
        Ws[buf][kk4+0][mm+32]=w1.x; Ws[buf][kk4+1][mm+32]=w1.y; Ws[buf][kk4+2][mm+32]=w1.z; Ws[buf][kk4+3][mm+32]=w1.w; }

    STAGE_G(0, 0);
    __syncthreads();
    #pragma unroll
    for (int ch = 0; ch < 2; ch++) {
        int buf = ch & 1;
        if (ch < 1) STAGE_G(1, 32);
        #pragma unroll
        for (int kk = 0; kk < 32; kk++) {
            float4 a = *(const float4*)&As[buf][kk][tx*4];
            ulonglong2 w = *(const ulonglong2*)&Ws[buf][kk][ty*4];
            unsigned long long a0 = dup2(a.x), a1 = dup2(a.y), a2 = dup2(a.z), a3 = dup2(a.w);
            ffma2(acc[0][0], a0, w.x); ffma2(acc[0][1], a0, w.y);
            ffma2(acc[1][0], a1, w.x); ffma2(acc[1][1], a1, w.y);
            ffma2(acc[2][0], a2, w.x); ffma2(acc[2][1], a2, w.y);
            ffma2(acc[3][0], a3, w.x); ffma2(acc[3][1], a3, w.y);
        }
        __syncthreads();
    }
    int u0 = n0 + ty*4;
    float4 b4 = *(const float4*)&bgh[u0];
    #pragma unroll
    for (int mi = 0; mi < 4; mi++) {
        int row = m0 + tx*4 + mi;
        float2 p0 = upk2(acc[mi][0]), p1 = upk2(acc[mi][1]);
        float4 v;
        v.x = expf(-fmaxf(p0.x + b4.x, 0.f));
        v.y = expf(-fmaxf(p0.y + b4.y, 0.f));
        v.z = expf(-fmaxf(p1.x + b4.z, 0.f));
        v.w = expf(-fmaxf(p1.y + b4.w, 0.f));
        *(float4*)&g_gh[row*H_ + u0] = v;
    }
    #undef STAGE_G
}

__global__ void k_alpha(const float* __restrict__ bgx, const float* __restrict__ bcomb) {
    __shared__ float gx[4][C_], ms[4][C_];
    int row0 = blockIdx.x * 8;
    int r = threadIdx.x >> 6, i = threadIdx.x & 63;
    for (int p = 0; p < 2; p++) {
        int row = row0 + p*4 + r;
        float d = g_d[row*C_ + i], m = g_m[row*C_ + i];
        gx[r][i] = expf(-fmaxf(d*g_diag[i] + bgx[i], 0.f));
        ms[r][i] = m;
        __syncthreads();
        float acc = bcomb[i];
        #pragma unroll 8
        for (int j = 0; j < C_; j++) acc += gx[r][j] * g_WcT[j*C_ + i];
        #pragma unroll 8
        for (int j = 0; j < C_; j++) acc += ms[r][j] * g_WcT[(C_ + j)*C_ + i];
        g_al[row*C_ + i] = acc;
        __syncthreads();
    }
}

// ======================= persistent sequential kernel =======================
// smem layout (floats)
#define SW_OFF   0                       // W slice [640][68]
#define SW_SZ    (K_*68)                 // 43520
#define AST_OFF  (SW_OFF + SW_SZ)        // dup-A: [buf][Lo 32x68 | Hi 32x68]
#define AST_SZ   (2*2*32*68)             // 8704 (also aliased as phase-A partials)
#define HD_OFF   (AST_OFF + AST_SZ)      // 2*512
#define XH_OFF   (HD_OFF + 2*H_)
#define XC_OFF   (XH_OFF + 2*C_)
#define MS_OFF   (XC_OFF + 2*C_)
#define VS_OFF   (MS_OFF + 2*C_)
#define SMEM_FLOATS (VS_OFF + 2*C_)      // 53760 floats = 215040 B

__global__ void __launch_bounds__(256, 1) k_seq(const float* __restrict__ bhist,
                                                const float* __restrict__ bfeat,
                                                float* __restrict__ out) {
    extern __shared__ __align__(16) float sm[];
    float* Wsm  = sm + SW_OFF;
    float* Ast  = sm + AST_OFF;
    float* hd   = sm + HD_OFF;
    float* xh   = sm + XH_OFF;
    float* xc   = sm + XC_OFF;
    float* msh  = sm + MS_OFF;
    float* vsh  = sm + VS_OFF;

    int tid = threadIdx.x, blk = blockIdx.x;
    int grp = blk & 3, nt = blk >> 2;
    int m0 = grp << 6, n0 = nt << 6;
    int tx = tid & 15, ty = tid >> 4;
    int mm = tid >> 3, kk4 = (tid & 7) << 2;
    int b0 = m0 + nt*2;                  // phase-A rows inside own group

    // prologue: W slice to smem (once), bias + cell state in regs
    for (int i = tid; i < 64*K_; i += 256) {
        int nl = i / K_, k = i - nl*K_;
        Wsm[k*68 + nl] = g_Wcat[(n0 + nl)*K_ + k];
    }
    float4 bq = *(const float4*)&g_bias[n0 + ty*4];
    int u_ep = (n0 + ty*4) >> 2;
    float cst[4] = {0.f, 0.f, 0.f, 0.f};
    __syncthreads();

    for (int t = 0; t < T_; t++) {
        // ---------------- phase A ----------------
        if (tid < 128) {
            int r = tid >> 6, c = tid & 63;
            int o = (t*B_ + b0 + r)*C_ + c;
            msh[tid] = g_m[o]; vsh[tid] = g_v[o];
        }
        {
            int r = tid >> 7, u0 = (tid & 127) * 4;
            int b = b0 + r;
            float4 h4 = __ldcg((const float4*)&g_h[b*H_ + u0]);
            float4 gh4 = *(const float4*)&g_gh[(t*B_ + b)*H_ + u0];
            float4 v = make_float4(h4.x*gh4.x, h4.y*gh4.y, h4.z*gh4.z, h4.w*gh4.w);
            *(float4*)&hd[r*H_ + u0] = v;
            __stcg((float4*)&g_A[b*K_ + u0], v);
        }
        __syncthreads();
        {   // x_h GEMV v2: thread (uc = tid>>4: 16 u-chunks of 32, c4 = tid&15)
            int uc = tid >> 4, c4 = tid & 15;
            const float4* wp = (const float4*)&g_WhT[(uc*32)*C_ + c4*4];
            const float* h0 = &hd[uc*32];
            const float* h1 = &hd[H_ + uc*32];
            float4 a0 = make_float4(0.f,0.f,0.f,0.f);
            float4 a1 = make_float4(0.f,0.f,0.f,0.f);
            #pragma unroll 8
            for (int u = 0; u < 32; u++) {
                float4 w = wp[u*16];     // stride C_/4 float4 between u's
                float ha = h0[u], hb = h1[u];
                a0.x += ha*w.x; a0.y += ha*w.y; a0.z += ha*w.z; a0.w += ha*w.w;
                a1.x += hb*w.x; a1.y += hb*w.y; a1.z += hb*w.z; a1.w += hb*w.w;
            }
            *(float4*)&Ast[uc*64 + c4*4]        = a0;   // partials alias Ast
            *(float4*)&Ast[1024 + uc*64 + c4*4] = a1;
        }
        __syncthreads();
        if (tid < 128) {
            int r = tid >> 6, c = tid & 63;
            float s = bhist[c];
            #pragma unroll
            for (int uc = 0; uc < 16; uc++) s += Ast[r*1024 + uc*64 + c];
            xh[tid] = s;
            float m = msh[tid], v = vsh[tid];
            xc[tid] = m*v + (1.f - m)*s;
        }
        __syncthreads();
        if (tid < 128) {
            int r = tid >> 6, i = tid & 63;
            int b = b0 + r;
            float z = bfeat[i];
            const float* xp = &xc[r*C_];
            #pragma unroll 16
            for (int j = 0; j < C_; j++) z += xp[j] * g_WfT[j*C_ + i];
            float al = g_al[(t*B_ + b)*C_ + i];
            float x_h = xh[tid];
            float ch = al*z + (1.f - al)*x_h;
            float m = msh[tid], v = vsh[tid];
            float cc = m*v + (1.f - m)*ch;
            out[(b*T_ + t)*C_ + i] = cc;
            __stcg(&g_A[b*K_ + H_ + i], cc);
            __stcg(&g_A[b*K_ + H_ + C_ + i], m);
        }
        gbar(grp);   // group's g_A complete

        // ---------------- phase B: 64x64 tile, dup-A Lo/Hi, no inner MOVs ----------------
        unsigned long long acc[4][2] = {};
        // rows tx*4..+3: pairs (4tx,4tx+1) in Lo[tx*4..+3], (4tx+2,4tx+3) in Hi
        #define STAGE_A(buf, kc) { \
            float4 a0 = __ldcg((const float4*)&g_A[(m0+mm)*K_ + (kc) + kk4]); \
            float4 a1 = __ldcg((const float4*)&g_A[(m0+mm+32)*K_ + (kc) + kk4]); \
            float* arr = Ast + (buf)*4352 + ((mm & 2) ? 2176 : 0); \
            int boff = (mm >> 2)*4 + (mm & 1)*2; \
            float av[4] = {a0.x, a0.y, a0.z, a0.w}; \
            float bv[4] = {a1.x, a1.y, a1.z, a1.w}; \
            _Pragma("unroll") \
            for (int i2 = 0; i2 < 4; i2++) { \
                float* p = &arr[(kk4 + i2)*68 + boff]; \
                p[0] = av[i2]; p[1] = av[i2]; \
                p[32] = bv[i2]; p[33] = bv[i2]; \
            } }

        STAGE_A(0, 0);
        __syncthreads();
        for (int ch = 0; ch < 20; ch++) {
            int buf = ch & 1;
            if (ch < 19) STAGE_A(buf ^ 1, (ch + 1) * 32);
            const float* Alo = Ast + buf*4352;
            const float* Ahi = Alo + 2176;
            const float* Wb = Wsm + (ch*32)*68;
            #pragma unroll
            for (int kk = 0; kk < 32; kk++) {
                ulonglong2 lo = *(const ulonglong2*)&Alo[kk*68 + tx*4];
                ulonglong2 hi = *(const ulonglong2*)&Ahi[kk*68 + tx*4];
                ulonglong2 w  = *(const ulonglong2*)&Wb[kk*68 + ty*4];
                ffma2(acc[0][0], lo.x, w.x); ffma2(acc[0][1], lo.x, w.y);
                ffma2(acc[1][0], lo.y, w.x); ffma2(acc[1][1], lo.y, w.y);
                ffma2(acc[2][0], hi.x, w.x); ffma2(acc[2][1], hi.x, w.y);
                ffma2(acc[3][0], hi.y, w.x); ffma2(acc[3][1], hi.y, w.y);
            }
            __syncthreads();
        }
        #undef STAGE_A

        // LSTM epilogue: this thread's 4 N-cols = one unit's (i,f,g,o)
        #pragma unroll
        for (int mi = 0; mi < 4; mi++) {
            int b = m0 + tx*4 + mi;
            float2 p0 = upk2(acc[mi][0]), p1 = upk2(acc[mi][1]);
            float gi = p0.x + bq.x;
            float gf = p0.y + bq.y;
            float gg = p1.x + bq.z;
            float go = p1.y + bq.w;
            float co = cst[mi];
            float si = 1.f/(1.f + expf(-gi));
            float sf = 1.f/(1.f + expf(-gf));
            float so = 1.f/(1.f + expf(-go));
            float cn = sf*co + si*tanhf(gg);
            cst[mi] = cn;
            __stcg(&g_h[b*H_ + u_ep], so*tanhf(cn));
        }
        gbar(grp);   // group's g_h complete
    }
}

extern "C" void kernel_launch(void* const* d_in, const int* in_sizes, int n_in,
                              void* d_out, int out_size) {
    const float* data  = (const float*)d_in[0];
    const float* Wih   = (const float*)d_in[1];
    const float* Whh   = (const float*)d_in[2];
    const float* bih   = (const float*)d_in[3];
    const float* bhh   = (const float*)d_in[4];
    const float* Wgh   = (const float*)d_in[5];
    const float* bgh   = (const float*)d_in[6];
    const float* Wgx   = (const float*)d_in[7];
    const float* bgx   = (const float*)d_in[8];
    const float* Whist = (const float*)d_in[9];
    const float* bhist = (const float*)d_in[10];
    const float* Wfeat = (const float*)d_in[11];
    const float* bfeat = (const float*)d_in[12];
    const float* Wcomb = (const float*)d_in[13];
    const float* bcomb = (const float*)d_in[14];
    float* out = (float*)d_out;

    static int smem_set = 0;
    if (!smem_set) {
        cudaFuncSetAttribute(k_seq, cudaFuncAttributeMaxDynamicSharedMemorySize,
                             SMEM_FLOATS * sizeof(float));
        smem_set = 1;
    }

    k_pack_w<<<2048, 256>>>(Wih, Whh);
    k_pack_misc<<<256, 256>>>(Whist, Wfeat, Wcomb, bih, bhh, Wgx);
    k_prep<<<64, 256>>>(data);
    k_gammaH<<<8192, 256>>>(Wgh, bgh);
    k_alpha<<<8192, 256>>>(bgx, bcomb);
    k_seq<<<NBLK, 256, SMEM_FLOATS * sizeof(float)>>>(bhist, bfeat, out);
}

// round 11
// speedup vs baseline: 2.0616x; 1.1781x over previous
#include <cuda_runtime.h>
#include <math.h>

#define T_ 256
#define B_ 256
#define C_ 64
#define H_ 512
#define G_ 2048
#define K_ 640   // 512 (h) + 64 (c_c) + 64 (m)
#define NBLK 128

// ---- static device scratch ----
__device__ float g_v[T_*B_*C_];
__device__ float g_m[T_*B_*C_];
__device__ float g_d[T_*B_*C_];
__device__ float g_gh[T_*B_*H_];    // gamma_h (134MB)
__device__ float g_al[T_*B_*C_];
__device__ float g_A[B_*K_];        // [h_dec | c_c | m]
__device__ float g_h[B_*H_];
__device__ float g_Wcat[G_*K_];     // [u*4+gate][k]
__device__ float g_bias[G_];
__device__ float g_WhT[H_*C_];
__device__ float g_WfT[C_*C_];
__device__ float g_WcT[2*C_*C_];
__device__ float g_diag[C_];
__device__ unsigned g_arrive;
__device__ unsigned g_gen;

// ---- f32x2 packed FMA helpers ----
__device__ __forceinline__ unsigned long long dup2(float a) {
    unsigned long long r;
    asm("mov.b64 %0, {%1,%1};" : "=l"(r) : "f"(a));
    return r;
}
__device__ __forceinline__ void ffma2(unsigned long long& d, unsigned long long a,
                                      unsigned long long b) {
    asm("fma.rn.f32x2 %0, %1, %2, %0;" : "+l"(d) : "l"(a), "l"(b));
}
__device__ __forceinline__ float2 upk2(unsigned long long v) {
    float2 f;
    asm("mov.b64 {%0,%1}, %2;" : "=f"(f.x), "=f"(f.y) : "l"(v));
    return f;
}

// ---- grid barrier (R7 semantics; waiters poll with acquire LOADS, not RMWs) ----
__device__ __forceinline__ void gbar() {
    __threadfence();          // publish stores + L1 coherence point
    __syncthreads();
    if (threadIdx.x == 0) {
        unsigned gen;
        asm volatile("ld.acquire.gpu.global.u32 %0, [%1];" : "=r"(gen) : "l"(&g_gen));
        unsigned a = atomicAdd(&g_arrive, 1u);
        if (a == NBLK - 1) {
            atomicExch(&g_arrive, 0u);
            __threadfence();
            atomicAdd(&g_gen, 1u);
        } else {
            unsigned g;
            do {
                __nanosleep(64);
                asm volatile("ld.acquire.gpu.global.u32 %0, [%1];" : "=r"(g) : "l"(&g_gen));
            } while (g == gen);
        }
    }
    __syncthreads();
}

// ======================= preamble kernels (3 launches) =======================

// launch #1: all weight packing
__global__ void k_pack(const float* __restrict__ Wih,   const float* __restrict__ Whh,
                       const float* __restrict__ Whist, const float* __restrict__ Wfeat,
                       const float* __restrict__ Wcomb, const float* __restrict__ bih,
                       const float* __restrict__ bhh,   const float* __restrict__ Wgx) {
    int tid = blockIdx.x*blockDim.x + threadIdx.x, n = gridDim.x*blockDim.x;
    for (int i = tid; i < G_*K_; i += n) {
        int gp = i / K_, k = i % K_;
        int u = gp >> 2, gate = gp & 3;
        int go = gate*H_ + u;
        float w;
        if (k < H_)            w = Whh[go*H_ + k];
        else if (k < H_ + C_)  w = Wih[go*2*C_ + (k - H_)];
        else                   w = Wih[go*2*C_ + C_ + (k - H_ - C_)];
        g_Wcat[i] = w;
    }
    for (int i = tid; i < H_*C_; i += n) { int u=i/C_, c=i%C_; g_WhT[i] = Whist[c*H_ + u]; }
    for (int i = tid; i < C_*C_; i += n) { int j=i/C_, c=i%C_; g_WfT[i] = (j==c)?0.f:Wfeat[c*C_ + j]; }
    for (int i = tid; i < 2*C_*C_; i += n) { int j=i/C_, c=i%C_; g_WcT[i] = Wcomb[c*2*C_ + j]; }
    for (int i = tid; i < C_; i += n) g_diag[i] = Wgx[i*C_ + i];
    for (int i = tid; i < G_; i += n) { int u=i>>2, g=i&3; int go=g*H_+u; g_bias[i] = bih[go] + bhh[go]; }
    for (int i = tid; i < B_*H_; i += n) g_h[i] = 0.f;
}

// launch #2: masks/values/deltas
__global__ void k_prep(const float* __restrict__ data) {
    int id = blockIdx.x*blockDim.x + threadIdx.x;
    if (id >= B_*C_) return;
    int b = id / C_, c = id % C_;
    float dec = 1.f, m_prev = 1.f;
    for (int t = 0; t < T_; t++) {
        float x = data[(b*T_ + t)*C_ + c];
        float m = (x != x) ? 0.f : 1.f;
        float v = (x != x) ? 0.f : x;
        float del;
        if (t == 0) del = 0.f;
        else if (t == 1) del = 1.f;
        else { dec = (m_prev == 1.f) ? 1.f : dec + 1.f; del = dec; }
        int o = (t*B_ + b)*C_ + c;
        g_v[o] = v; g_m[o] = m; g_d[o] = del;
        m_prev = m;
    }
}

// launch #3: fused gamma_h GEMM tile + alpha rows (both depend only on prep)
__global__ void __launch_bounds__(256) k_ga(const float* __restrict__ Wgh,
                                            const float* __restrict__ bgh,
                                            const float* __restrict__ bgx,
                                            const float* __restrict__ bcomb) {
    __shared__ __align__(16) float As[2][32][68];
    __shared__ __align__(16) float Ws[2][32][68];
    __shared__ float gx[4][C_], ms[4][C_];
    int m0 = (blockIdx.x >> 3) << 6;
    int n0 = (blockIdx.x & 7) << 6;
    int tid = threadIdx.x, tx = tid & 15, ty = tid >> 4;
    int mm = tid >> 3, kk4 = (tid & 7) << 2;

    // --- gamma_h tile: [65536 x 64] @ [64 x 512]^T ---
    unsigned long long acc[4][2] = {};
    #define STAGE_G(buf, kc) { \
        float4 a0 = *(const float4*)&g_d[(m0+mm)*C_ + (kc) + kk4]; \
        float4 a1 = *(const float4*)&g_d[(m0+mm+32)*C_ + (kc) + kk4]; \
        float4 w0 = *(const float4*)&Wgh[(n0+mm)*C_ + (kc) + kk4]; \
        float4 w1 = *(const float4*)&Wgh[(n0+mm+32)*C_ + (kc) + kk4]; \
        As[buf][kk4+0][mm]=a0.x; As[buf][kk4+1][mm]=a0.y; As[buf][kk4+2][mm]=a0.z; As[buf][kk4+3][mm]=a0.w; \
        As[buf][kk4+0][mm+32]=a1.x; As[buf][kk4+1][mm+32]=a1.y; As[buf][kk4+2][mm+32]=a1.z; As[buf][kk4+3][mm+32]=a1.w; \
        Ws[buf][kk4+0][mm]=w0.x; Ws[buf][kk4+1][mm]=w0.y; Ws[buf][kk4+2][mm]=w0.z; Ws[buf][kk4+3][mm]=w0.w; \
        Ws[buf][kk4+0][mm+32]=w1.x; Ws[buf][kk4+1][mm+32]=w1.y; Ws[buf][kk4+2][mm+32]=w1.z; Ws[buf][kk4+3][mm+32]=w1.w; }

    STAGE_G(0, 0);
    __syncthreads();
    #pragma unroll
    for (int ch = 0; ch < 2; ch++) {
        int buf = ch & 1;
        if (ch < 1) STAGE_G(1, 32);
        #pragma unroll
        for (int kk = 0; kk < 32; kk++) {
            float4 a = *(const float4*)&As[buf][kk][tx*4];
            ulonglong2 w = *(const ulonglong2*)&Ws[buf][kk][ty*4];
            unsigned long long a0 = dup2(a.x), a1 = dup2(a.y), a2 = dup2(a.z), a3 = dup2(a.w);
            ffma2(acc[0][0], a0, w.x); ffma2(acc[0][1], a0, w.y);
            ffma2(acc[1][0], a1, w.x); ffma2(acc[1][1], a1, w.y);
            ffma2(acc[2][0], a2, w.x); ffma2(acc[2][1], a2, w.y);
            ffma2(acc[3][0], a3, w.x); ffma2(acc[3][1], a3, w.y);
        }
        __syncthreads();
    }
    int u0 = n0 + ty*4;
    float4 b4 = *(const float4*)&bgh[u0];
    #pragma unroll
    for (int mi = 0; mi < 4; mi++) {
        int row = m0 + tx*4 + mi;
        float2 p0 = upk2(acc[mi][0]), p1 = upk2(acc[mi][1]);
        float4 v;
        v.x = expf(-fmaxf(p0.x + b4.x, 0.f));
        v.y = expf(-fmaxf(p0.y + b4.y, 0.f));
        v.z = expf(-fmaxf(p1.x + b4.z, 0.f));
        v.w = expf(-fmaxf(p1.y + b4.w, 0.f));
        *(float4*)&g_gh[row*H_ + u0] = v;
    }
    #undef STAGE_G

    // --- alpha: 8 rows per block ---
    __syncthreads();
    int row0 = blockIdx.x * 8;
    int r = tid >> 6, i = tid & 63;
    for (int p = 0; p < 2; p++) {
        int row = row0 + p*4 + r;
        float d = g_d[row*C_ + i], m = g_m[row*C_ + i];
        gx[r][i] = expf(-fmaxf(d*g_diag[i] + bgx[i], 0.f));
        ms[r][i] = m;
        __syncthreads();
        float acc2 = bcomb[i];
        #pragma unroll 8
        for (int j = 0; j < C_; j++) acc2 += gx[r][j] * g_WcT[j*C_ + i];
        #pragma unroll 8
        for (int j = 0; j < C_; j++) acc2 += ms[r][j] * g_WcT[(C_ + j)*C_ + i];
        g_al[row*C_ + i] = acc2;
        __syncthreads();
    }
}

// ======================= persistent sequential kernel (exact R7) =======================
#define SW_OFF   0
#define SW_SZ    (K_*68)
#define AS_OFF   (SW_OFF + SW_SZ)
#define AS_SZ    (2*32*68)
#define HD_OFF   (AS_OFF + AS_SZ)
#define PART_OFF (HD_OFF + 2*H_)
#define XH_OFF   (PART_OFF + 256)
#define XC_OFF   (XH_OFF + 2*C_)
#define MS_OFF   (XC_OFF + 2*C_)
#define VS_OFF   (MS_OFF + 2*C_)
#define SMEM_FLOATS (VS_OFF + 2*C_)      // 49664 floats = 198656 B

__global__ void __launch_bounds__(256, 1) k_seq(const float* __restrict__ bhist,
                                                const float* __restrict__ bfeat,
                                                float* __restrict__ out) {
    extern __shared__ __align__(16) float sm[];
    float* Wsm  = sm + SW_OFF;
    float* As   = sm + AS_OFF;
    float* hd   = sm + HD_OFF;
    float* part = sm + PART_OFF;
    float* xh   = sm + XH_OFF;
    float* xc   = sm + XC_OFF;
    float* msh  = sm + MS_OFF;
    float* vsh  = sm + VS_OFF;

    int tid = threadIdx.x, blk = blockIdx.x;
    int m0 = (blk & 3) << 6, n0 = (blk >> 2) << 6;
    int tx = tid & 15, ty = tid >> 4;
    int mm = tid >> 3, kk4 = (tid & 7) << 2;
    int b0 = blk * 2;

    for (int i = tid; i < 64*K_; i += 256) {
        int nl = i / K_, k = i - nl*K_;
        Wsm[k*68 + nl] = g_Wcat[(n0 + nl)*K_ + k];
    }
    float4 bq = *(const float4*)&g_bias[n0 + ty*4];
    int u_ep = (n0 + ty*4) >> 2;
    float cst[4] = {0.f, 0.f, 0.f, 0.f};
    __syncthreads();

    for (int t = 0; t < T_; t++) {
        // ---------------- phase A ----------------
        if (tid < 128) {
            int r = tid >> 6, c = tid & 63;
            int o = (t*B_ + b0 + r)*C_ + c;
            msh[tid] = g_m[o]; vsh[tid] = g_v[o];
        }
        {
            int r = tid >> 7, u0 = (tid & 127) * 4;
            int b = b0 + r;
            float4 h4 = *(const float4*)&g_h[b*H_ + u0];
            float4 gh4 = *(const float4*)&g_gh[(t*B_ + b)*H_ + u0];
            float4 v = make_float4(h4.x*gh4.x, h4.y*gh4.y, h4.z*gh4.z, h4.w*gh4.w);
            *(float4*)&hd[r*H_ + u0] = v;
            *(float4*)&g_A[b*K_ + u0] = v;
        }
        __syncthreads();
        {
            int r = tid >> 7, half = (tid >> 6) & 1, c = tid & 63;
            const float* hp = &hd[r*H_ + half*256];
            const float* wp = &g_WhT[(half*256)*C_ + c];
            float a0 = 0.f, a1 = 0.f, a2 = 0.f, a3 = 0.f;
            #pragma unroll 8
            for (int u = 0; u < 256; u += 4) {
                a0 += hp[u+0] * wp[(u+0)*C_];
                a1 += hp[u+1] * wp[(u+1)*C_];
                a2 += hp[u+2] * wp[(u+2)*C_];
                a3 += hp[u+3] * wp[(u+3)*C_];
            }
            part[tid] = (a0 + a1) + (a2 + a3);
        }
        __syncthreads();
        if (tid < 128) {
            int r = tid >> 6, c = tid & 63;
            float x_h = part[r*128 + c] + part[r*128 + 64 + c] + bhist[c];
            xh[tid] = x_h;
            float m = msh[tid], v = vsh[tid];
            xc[tid] = m*v + (1.f - m)*x_h;
        }
        __syncthreads();
        if (tid < 128) {
            int r = tid >> 6, i = tid & 63;
            int b = b0 + r;
            float z = bfeat[i];
            const float* xp = &xc[r*C_];
            #pragma unroll 8
            for (int j = 0; j < C_; j++) z += xp[j] * g_WfT[j*C_ + i];
            float al = g_al[(t*B_ + b)*C_ + i];
            float x_h = xh[tid];
            float ch = al*z + (1.f - al)*x_h;
            float m = msh[tid], v = vsh[tid];
            float cc = m*v + (1.f - m)*ch;
            out[(b*T_ + t)*C_ + i] = cc;
            g_A[b*K_ + H_ + i] = cc;
            g_A[b*K_ + H_ + C_ + i] = m;
        }
        gbar();   // g_A complete chip-wide

        // ---------------- phase B ----------------
        unsigned long long acc[4][2] = {};
        #define STAGE_A(buf, kc) { \
            float4 a0 = *(const float4*)&g_A[(m0+mm)*K_ + (kc) + kk4]; \
            float4 a1 = *(const float4*)&g_A[(m0+mm+32)*K_ + (kc) + kk4]; \
            float* Ab = As + (buf)*(32*68); \
            Ab[(kk4+0)*68+mm]=a0.x; Ab[(kk4+1)*68+mm]=a0.y; Ab[(kk4+2)*68+mm]=a0.z; Ab[(kk4+3)*68+mm]=a0.w; \
            Ab[(kk4+0)*68+mm+32]=a1.x; Ab[(kk4+1)*68+mm+32]=a1.y; Ab[(kk4+2)*68+mm+32]=a1.z; Ab[(kk4+3)*68+mm+32]=a1.w; }

        STAGE_A(0, 0);
        __syncthreads();
        for (int ch = 0; ch < 20; ch++) {
            int buf = ch & 1;
            if (ch < 19) STAGE_A(buf ^ 1, (ch + 1) * 32);
            const float* Ab = As + buf*(32*68);
            const float* Wb = Wsm + (ch*32)*68;
            #pragma unroll
            for (int kk = 0; kk < 32; kk++) {
                float4 a = *(const float4*)&Ab[kk*68 + tx*4];
                ulonglong2 w = *(const ulonglong2*)&Wb[kk*68 + ty*4];
                unsigned long long a0 = dup2(a.x), a1 = dup2(a.y), a2 = dup2(a.z), a3 = dup2(a.w);
                ffma2(acc[0][0], a0, w.x); ffma2(acc[0][1], a0, w.y);
                ffma2(acc[1][0], a1, w.x); ffma2(acc[1][1], a1, w.y);
                ffma2(acc[2][0], a2, w.x); ffma2(acc[2][1], a2, w.y);
                ffma2(acc[3][0], a3, w.x); ffma2(acc[3][1], a3, w.y);
            }
            __syncthreads();
        }
        #undef STAGE_A

        // LSTM epilogue
        #pragma unroll
        for (int mi = 0; mi < 4; mi++) {
            int b = m0 + tx*4 + mi;
            float2 p0 = upk2(acc[mi][0]), p1 = upk2(acc[mi][1]);
            float gi = p0.x + bq.x;
            float gf = p0.y + bq.y;
            float gg = p1.x + bq.z;
            float go = p1.y + bq.w;
            float co = cst[mi];
            float si = 1.f/(1.f + expf(-gi));
            float sf = 1.f/(1.f + expf(-gf));
            float so = 1.f/(1.f + expf(-go));
            float cn = sf*co + si*tanhf(gg);
            cst[mi] = cn;
            g_h[b*H_ + u_ep] = so*tanhf(cn);
        }
        gbar();   // g_h complete chip-wide
    }
}

extern "C" void kernel_launch(void* const* d_in, const int* in_sizes, int n_in,
                              void* d_out, int out_size) {
    const float* data  = (const float*)d_in[0];
    const float* Wih   = (const float*)d_in[1];
    const float* Whh   = (const float*)d_in[2];
    const float* bih   = (const float*)d_in[3];
    const float* bhh   = (const float*)d_in[4];
    const float* Wgh   = (const float*)d_in[5];
    const float* bgh   = (const float*)d_in[6];
    const float* Wgx   = (const float*)d_in[7];
    const float* bgx   = (const float*)d_in[8];
    const float* Whist = (const float*)d_in[9];
    const float* bhist = (const float*)d_in[10];
    const float* Wfeat = (const float*)d_in[11];
    const float* bfeat = (const float*)d_in[12];
    const float* Wcomb = (const float*)d_in[13];
    const float* bcomb = (const float*)d_in[14];
    float* out = (float*)d_out;

    static int smem_set = 0;
    if (!smem_set) {
        cudaFuncSetAttribute(k_seq, cudaFuncAttributeMaxDynamicSharedMemorySize,
                             SMEM_FLOATS * sizeof(float));
        smem_set = 1;
    }

    k_pack<<<2048, 256>>>(Wih, Whh, Whist, Wfeat, Wcomb, bih, bhh, Wgx);   // #1
    k_prep<<<64, 256>>>(data);                                             // #2
    k_ga<<<8192, 256>>>(Wgh, bgh, bgx, bcomb);                             // #3
    k_seq<<<NBLK, 256, SMEM_FLOATS * sizeof(float)>>>(bhist, bfeat, out);  // #4 (profiled slot)
}

// round 12
// speedup vs baseline: 2.0739x; 1.0060x over previous
#include <cuda_runtime.h>
#include <math.h>

#define T_ 256
#define B_ 256
#define C_ 64
#define H_ 512
#define G_ 2048
#define K_ 640   // 512 (h) + 64 (c_c) + 64 (m)
#define NBLK 128

// ---- static device scratch ----
__device__ float g_v[T_*B_*C_];
__device__ float g_m[T_*B_*C_];
__device__ float g_d[T_*B_*C_];
__device__ float g_gh[T_*B_*H_];    // gamma_h (134MB)
__device__ float g_al[T_*B_*C_];
__device__ float g_A[B_*128];       // [c_c | m] only (h part staged from g_h*g_gh)
__device__ float g_h[B_*H_];
__device__ float g_Wcat[G_*K_];     // [u*4+gate][k]
__device__ float g_bias[G_];
__device__ float g_WhT[H_*C_];
__device__ float g_WfT[C_*C_];
__device__ float g_WcT[2*C_*C_];
__device__ float g_diag[C_];
__device__ unsigned g_arrive;
__device__ unsigned g_gen;

// ---- f32x2 packed FMA helpers ----
__device__ __forceinline__ unsigned long long dup2(float a) {
    unsigned long long r;
    asm("mov.b64 %0, {%1,%1};" : "=l"(r) : "f"(a));
    return r;
}
__device__ __forceinline__ void ffma2(unsigned long long& d, unsigned long long a,
                                      unsigned long long b) {
    asm("fma.rn.f32x2 %0, %1, %2, %0;" : "+l"(d) : "l"(a), "l"(b));
}
__device__ __forceinline__ float2 upk2(unsigned long long v) {
    float2 f;
    asm("mov.b64 {%0,%1}, %2;" : "=f"(f.x), "=f"(f.y) : "l"(v));
    return f;
}

// ---- grid barrier (proven R7/R11 version) ----
__device__ __forceinline__ void gbar() {
    __threadfence();          // publish stores + L1 coherence point
    __syncthreads();
    if (threadIdx.x == 0) {
        unsigned gen;
        asm volatile("ld.acquire.gpu.global.u32 %0, [%1];" : "=r"(gen) : "l"(&g_gen));
        unsigned a = atomicAdd(&g_arrive, 1u);
        if (a == NBLK - 1) {
            atomicExch(&g_arrive, 0u);
            __threadfence();
            atomicAdd(&g_gen, 1u);
        } else {
            unsigned g;
            do {
                __nanosleep(64);
                asm volatile("ld.acquire.gpu.global.u32 %0, [%1];" : "=r"(g) : "l"(&g_gen));
            } while (g == gen);
        }
    }
    __syncthreads();
}

// ======================= preamble kernels (3 launches) =======================

__global__ void k_pack(const float* __restrict__ Wih,   const float* __restrict__ Whh,
                       const float* __restrict__ Whist, const float* __restrict__ Wfeat,
                       const float* __restrict__ Wcomb, const float* __restrict__ bih,
                       const float* __restrict__ bhh,   const float* __restrict__ Wgx) {
    int tid = blockIdx.x*blockDim.x + threadIdx.x, n = gridDim.x*blockDim.x;
    for (int i = tid; i < G_*K_; i += n) {
        int gp = i / K_, k = i % K_;
        int u = gp >> 2, gate = gp & 3;
        int go = gate*H_ + u;
        float w;
        if (k < H_)            w = Whh[go*H_ + k];
        else if (k < H_ + C_)  w = Wih[go*2*C_ + (k - H_)];
        else                   w = Wih[go*2*C_ + C_ + (k - H_ - C_)];
        g_Wcat[i] = w;
    }
    for (int i = tid; i < H_*C_; i += n) { int u=i/C_, c=i%C_; g_WhT[i] = Whist[c*H_ + u]; }
    for (int i = tid; i < C_*C_; i += n) { int j=i/C_, c=i%C_; g_WfT[i] = (j==c)?0.f:Wfeat[c*C_ + j]; }
    for (int i = tid; i < 2*C_*C_; i += n) { int j=i/C_, c=i%C_; g_WcT[i] = Wcomb[c*2*C_ + j]; }
    for (int i = tid; i < C_; i += n) g_diag[i] = Wgx[i*C_ + i];
    for (int i = tid; i < G_; i += n) { int u=i>>2, g=i&3; int go=g*H_+u; g_bias[i] = bih[go] + bhh[go]; }
    for (int i = tid; i < B_*H_; i += n) g_h[i] = 0.f;
}

__global__ void k_prep(const float* __restrict__ data) {
    int id = blockIdx.x*blockDim.x + threadIdx.x;
    if (id >= B_*C_) return;
    int b = id / C_, c = id % C_;
    float dec = 1.f, m_prev = 1.f;
    for (int t = 0; t < T_; t++) {
        float x = data[(b*T_ + t)*C_ + c];
        float m = (x != x) ? 0.f : 1.f;
        float v = (x != x) ? 0.f : x;
        float del;
        if (t == 0) del = 0.f;
        else if (t == 1) del = 1.f;
        else { dec = (m_prev == 1.f) ? 1.f : dec + 1.f; del = dec; }
        int o = (t*B_ + b)*C_ + c;
        g_v[o] = v; g_m[o] = m; g_d[o] = del;
        m_prev = m;
    }
}

__global__ void __launch_bounds__(256) k_ga(const float* __restrict__ Wgh,
                                            const float* __restrict__ bgh,
                                            const float* __restrict__ bgx,
                                            const float* __restrict__ bcomb) {
    __shared__ __align__(16) float As[2][32][68];
    __shared__ __align__(16) float Ws[2][32][68];
    __shared__ float gx[4][C_], ms[4][C_];
    int m0 = (blockIdx.x >> 3) << 6;
    int n0 = (blockIdx.x & 7) << 6;
    int tid = threadIdx.x, tx = tid & 15, ty = tid >> 4;
    int mm = tid >> 3, kk4 = (tid & 7) << 2;

    unsigned long long acc[4][2] = {};
    #define STAGE_G(buf, kc) { \
        float4 a0 = *(const float4*)&g_d[(m0+mm)*C_ + (kc) + kk4]; \
        float4 a1 = *(const float4*)&g_d[(m0+mm+32)*C_ + (kc) + kk4]; \
        float4 w0 = *(const float4*)&Wgh[(n0+mm)*C_ + (kc) + kk4]; \
        float4 w1 = *(const float4*)&Wgh[(n0+mm+32)*C_ + (kc) + kk4]; \
        As[buf][kk4+0][mm]=a0.x; As[buf][kk4+1][mm]=a0.y; As[buf][kk4+2][mm]=a0.z; As[buf][kk4+3][mm]=a0.w; \
        As[buf][kk4+0][mm+32]=a1.x; As[buf][kk4+1][mm+32]=a1.y; As[buf][kk4+2][mm+32]=a1.z; As[buf][kk4+3][mm+32]=a1.w; \
        Ws[buf][kk4+0][mm]=w0.x; Ws[buf][kk4+1][mm]=w0.y; Ws[buf][kk4+2][mm]=w0.z; Ws[buf][kk4+3][mm]=w0.w; \
        Ws[buf][kk4+0][mm+32]=w1.x; Ws[buf][kk4+1][mm+32]=w1.y; Ws[buf][kk4+2][mm+32]=w1.z; Ws[buf][kk4+3][mm+32]=w1.w; }

    STAGE_G(0, 0);
    __syncthreads();
    #pragma unroll
    for (int ch = 0; ch < 2; ch++) {
        int buf = ch & 1;
        if (ch < 1) STAGE_G(1, 32);
        #pragma unroll
        for (int kk = 0; kk < 32; kk++) {
            float4 a = *(const float4*)&As[buf][kk][tx*4];
            ulonglong2 w = *(const ulonglong2*)&Ws[buf][kk][ty*4];
            unsigned long long a0 = dup2(a.x), a1 = dup2(a.y), a2 = dup2(a.z), a3 = dup2(a.w);
            ffma2(acc[0][0], a0, w.x); ffma2(acc[0][1], a0, w.y);
            ffma2(acc[1][0], a1, w.x); ffma2(acc[1][1], a1, w.y);
            ffma2(acc[2][0], a2, w.x); ffma2(acc[2][1], a2, w.y);
            ffma2(acc[3][0], a3, w.x); ffma2(acc[3][1], a3, w.y);
        }
        __syncthreads();
    }
    int u0 = n0 + ty*4;
    float4 b4 = *(const float4*)&bgh[u0];
    #pragma unroll
    for (int mi = 0; mi < 4; mi++) {
        int row = m0 + tx*4 + mi;
        float2 p0 = upk2(acc[mi][0]), p1 = upk2(acc[mi][1]);
        float4 v;
        v.x = expf(-fmaxf(p0.x + b4.x, 0.f));
        v.y = expf(-fmaxf(p0.y + b4.y, 0.f));
        v.z = expf(-fmaxf(p1.x + b4.z, 0.f));
        v.w = expf(-fmaxf(p1.y + b4.w, 0.f));
        *(float4*)&g_gh[row*H_ + u0] = v;
    }
    #undef STAGE_G

    __syncthreads();
    int row0 = blockIdx.x * 8;
    int r = tid >> 6, i = tid & 63;
    for (int p = 0; p < 2; p++) {
        int row = row0 + p*4 + r;
        float d = g_d[row*C_ + i], m = g_m[row*C_ + i];
        gx[r][i] = expf(-fmaxf(d*g_diag[i] + bgx[i], 0.f));
        ms[r][i] = m;
        __syncthreads();
        float acc2 = bcomb[i];
        #pragma unroll 8
        for (int j = 0; j < C_; j++) acc2 += gx[r][j] * g_WcT[j*C_ + i];
        #pragma unroll 8
        for (int j = 0; j < C_; j++) acc2 += ms[r][j] * g_WcT[(C_ + j)*C_ + i];
        g_al[row*C_ + i] = acc2;
        __syncthreads();
    }
}

// ======================= persistent sequential kernel =======================
#define SW_OFF   0
#define SW_SZ    (K_*68)
#define AS_OFF   (SW_OFF + SW_SZ)
#define AS_SZ    (2*32*68)
#define HD_OFF   (AS_OFF + AS_SZ)
#define PART_OFF (HD_OFF + 2*H_)
#define XH_OFF   (PART_OFF + 256)
#define XC_OFF   (XH_OFF + 2*C_)
#define MS_OFF   (XC_OFF + 2*C_)
#define VS_OFF   (MS_OFF + 2*C_)
#define SMEM_FLOATS (VS_OFF + 2*C_)      // 49664 floats = 198656 B

__global__ void __launch_bounds__(256, 1) k_seq(const float* __restrict__ bhist,
                                                const float* __restrict__ bfeat,
                                                float* __restrict__ out) {
    extern __shared__ __align__(16) float sm[];
    float* Wsm  = sm + SW_OFF;
    float* As   = sm + AS_OFF;
    float* hd   = sm + HD_OFF;
    float* part = sm + PART_OFF;
    float* xh   = sm + XH_OFF;
    float* xc   = sm + XC_OFF;
    float* msh  = sm + MS_OFF;
    float* vsh  = sm + VS_OFF;

    int tid = threadIdx.x, blk = blockIdx.x;
    int m0 = (blk & 3) << 6, n0 = (blk >> 2) << 6;
    int tx = tid & 15, ty = tid >> 4;
    int mm = tid >> 3, kk4 = (tid & 7) << 2;
    int b0 = blk * 2;

    for (int i = tid; i < 64*K_; i += 256) {
        int nl = i / K_, k = i - nl*K_;
        Wsm[k*68 + nl] = g_Wcat[(n0 + nl)*K_ + k];
    }
    float4 bq = *(const float4*)&g_bias[n0 + ty*4];
    int u_ep = (n0 + ty*4) >> 2;
    float cst[4] = {0.f, 0.f, 0.f, 0.f};
    __syncthreads();

    // staging: h-part chunks (k<512) computed on the fly from g_h * g_gh
    #define STAGE_H(buf, kc, tB) { \
        float4 h0 = *(const float4*)&g_h[(m0+mm)*H_ + (kc) + kk4]; \
        float4 q0 = *(const float4*)&g_gh[((tB) + m0 + mm)*H_ + (kc) + kk4]; \
        float4 h1 = *(const float4*)&g_h[(m0+mm+32)*H_ + (kc) + kk4]; \
        float4 q1 = *(const float4*)&g_gh[((tB) + m0 + mm + 32)*H_ + (kc) + kk4]; \
        float* Ab = As + (buf)*(32*68); \
        Ab[(kk4+0)*68+mm]=h0.x*q0.x; Ab[(kk4+1)*68+mm]=h0.y*q0.y; \
        Ab[(kk4+2)*68+mm]=h0.z*q0.z; Ab[(kk4+3)*68+mm]=h0.w*q0.w; \
        Ab[(kk4+0)*68+mm+32]=h1.x*q1.x; Ab[(kk4+1)*68+mm+32]=h1.y*q1.y; \
        Ab[(kk4+2)*68+mm+32]=h1.z*q1.z; Ab[(kk4+3)*68+mm+32]=h1.w*q1.w; }

    // staging: c_c|m chunks (k>=512) from compact g_A
    #define STAGE_C(buf, kcl) { \
        float4 a0 = *(const float4*)&g_A[(m0+mm)*128 + (kcl) + kk4]; \
        float4 a1 = *(const float4*)&g_A[(m0+mm+32)*128 + (kcl) + kk4]; \
        float* Ab = As + (buf)*(32*68); \
        Ab[(kk4+0)*68+mm]=a0.x; Ab[(kk4+1)*68+mm]=a0.y; Ab[(kk4+2)*68+mm]=a0.z; Ab[(kk4+3)*68+mm]=a0.w; \
        Ab[(kk4+0)*68+mm+32]=a1.x; Ab[(kk4+1)*68+mm+32]=a1.y; Ab[(kk4+2)*68+mm+32]=a1.z; Ab[(kk4+3)*68+mm+32]=a1.w; }

    #define INNER(buf, Wb) { \
        const float* Ab = As + (buf)*(32*68); \
        _Pragma("unroll") \
        for (int kk = 0; kk < 32; kk++) { \
            float4 a = *(const float4*)&Ab[kk*68 + tx*4]; \
            ulonglong2 w = *(const ulonglong2*)&(Wb)[kk*68 + ty*4]; \
            unsigned long long a0 = dup2(a.x), a1 = dup2(a.y), a2 = dup2(a.z), a3 = dup2(a.w); \
            ffma2(acc[0][0], a0, w.x); ffma2(acc[0][1], a0, w.y); \
            ffma2(acc[1][0], a1, w.x); ffma2(acc[1][1], a1, w.y); \
            ffma2(acc[2][0], a2, w.x); ffma2(acc[2][1], a2, w.y); \
            ffma2(acc[3][0], a3, w.x); ffma2(acc[3][1], a3, w.y); \
        } }

    for (int t = 0; t < T_; t++) {
        int tB = t * B_;
        // prefetch GEMM chunk 0 (depends only on g_h, ready now)
        STAGE_H(0, 0, tB);

        // ---------------- phase A (local rows b0, b0+1) ----------------
        if (tid < 128) {
            int r = tid >> 6, c = tid & 63;
            int o = (tB + b0 + r)*C_ + c;
            msh[tid] = g_m[o]; vsh[tid] = g_v[o];
        }
        {
            int r = tid >> 7, u0 = (tid & 127) * 4;
            int b = b0 + r;
            float4 h4 = *(const float4*)&g_h[b*H_ + u0];
            float4 gh4 = *(const float4*)&g_gh[(tB + b)*H_ + u0];
            float4 v = make_float4(h4.x*gh4.x, h4.y*gh4.y, h4.z*gh4.z, h4.w*gh4.w);
            *(float4*)&hd[r*H_ + u0] = v;
        }
        __syncthreads();
        {
            int r = tid >> 7, half = (tid >> 6) & 1, c = tid & 63;
            const float* hp = &hd[r*H_ + half*256];
            const float* wp = &g_WhT[(half*256)*C_ + c];
            float a0 = 0.f, a1 = 0.f, a2 = 0.f, a3 = 0.f;
            #pragma unroll 8
            for (int u = 0; u < 256; u += 4) {
                a0 += hp[u+0] * wp[(u+0)*C_];
                a1 += hp[u+1] * wp[(u+1)*C_];
                a2 += hp[u+2] * wp[(u+2)*C_];
                a3 += hp[u+3] * wp[(u+3)*C_];
            }
            part[tid] = (a0 + a1) + (a2 + a3);
        }
        __syncthreads();
        if (tid < 128) {
            int r = tid >> 6, c = tid & 63;
            float x_h = part[r*128 + c] + part[r*128 + 64 + c] + bhist[c];
            xh[tid] = x_h;
            float m = msh[tid], v = vsh[tid];
            xc[tid] = m*v + (1.f - m)*x_h;
        }
        __syncthreads();
        if (tid < 128) {
            int r = tid >> 6, i = tid & 63;
            int b = b0 + r;
            float z = bfeat[i];
            const float* xp = &xc[r*C_];
            #pragma unroll 8
            for (int j = 0; j < C_; j++) z += xp[j] * g_WfT[j*C_ + i];
            float al = g_al[(tB + b)*C_ + i];
            float x_h = xh[tid];
            float ch = al*z + (1.f - al)*x_h;
            float m = msh[tid], v = vsh[tid];
            float cc = m*v + (1.f - m)*ch;
            out[(b*T_ + t)*C_ + i] = cc;
            g_A[b*128 + i] = cc;
            g_A[b*128 + 64 + i] = m;
        }
        __syncthreads();   // As buf0 (STAGE_H above) complete for all threads

        // ---------------- GEMM h-part: 16 chunks, no barrier needed ----------------
        unsigned long long acc[4][2] = {};
        for (int ch = 0; ch < 16; ch++) {
            int buf = ch & 1;
            if (ch < 15) STAGE_H(buf ^ 1, (ch + 1) * 32, tB);
            INNER(buf, Wsm + (ch*32)*68);
            __syncthreads();
        }

        gbar();   // all blocks' c_c|m published

        // ---------------- GEMM c_c|m part: 4 chunks ----------------
        STAGE_C(0, 0);
        __syncthreads();
        for (int ch = 0; ch < 4; ch++) {
            int buf = ch & 1;
            if (ch < 3) STAGE_C(buf ^ 1, (ch + 1) * 32);
            INNER(buf, Wsm + ((16 + ch)*32)*68);
            __syncthreads();
        }

        // ---------------- LSTM epilogue ----------------
        #pragma unroll
        for (int mi = 0; mi < 4; mi++) {
            int b = m0 + tx*4 + mi;
            float2 p0 = upk2(acc[mi][0]), p1 = upk2(acc[mi][1]);
            float gi = p0.x + bq.x;
            float gf = p0.y + bq.y;
            float gg = p1.x + bq.z;
            float go = p1.y + bq.w;
            float co = cst[mi];
            float si = 1.f/(1.f + expf(-gi));
            float sf = 1.f/(1.f + expf(-gf));
            float so = 1.f/(1.f + expf(-go));
            float cn = sf*co + si*tanhf(gg);
            cst[mi] = cn;
            g_h[b*H_ + u_ep] = so*tanhf(cn);
        }
        gbar();   // g_h complete chip-wide
    }
    #undef STAGE_H
    #undef STAGE_C
    #undef INNER
}

extern "C" void kernel_launch(void* const* d_in, const int* in_sizes, int n_in,
                              void* d_out, int out_size) {
    const float* data  = (const float*)d_in[0];
    const float* Wih   = (const float*)d_in[1];
    const float* Whh   = (const float*)d_in[2];
    const float* bih   = (const float*)d_in[3];
    const float* bhh   = (const float*)d_in[4];
    const float* Wgh   = (const float*)d_in[5];
    const float* bgh   = (const float*)d_in[6];
    const float* Wgx   = (const float*)d_in[7];
    const float* bgx   = (const float*)d_in[8];
    const float* Whist = (const float*)d_in[9];
    const float* bhist = (const float*)d_in[10];
    const float* Wfeat = (const float*)d_in[11];
    const float* bfeat = (const float*)d_in[12];
    const float* Wcomb = (const float*)d_in[13];
    const float* bcomb = (const float*)d_in[14];
    float* out = (float*)d_out;

    static int smem_set = 0;
    if (!smem_set) {
        cudaFuncSetAttribute(k_seq, cudaFuncAttributeMaxDynamicSharedMemorySize,
                             SMEM_FLOATS * sizeof(float));
        smem_set = 1;
    }

    k_pack<<<2048, 256>>>(Wih, Whh, Whist, Wfeat, Wcomb, bih, bhh, Wgx);   // #1
    k_prep<<<64, 256>>>(data);                                             // #2
    k_ga<<<8192, 256>>>(Wgh, bgh, bgx, bcomb);                             // #3
    k_seq<<<NBLK, 256, SMEM_FLOATS * sizeof(float)>>>(bhist, bfeat, out);  // #4 (profiled slot)
}